// round 1
// baseline (speedup 1.0000x reference)
#include <cuda_runtime.h>
#include <math.h>

#define BATCH 2
#define SEQ 2048
#define DMODEL 1024
#define NHEAD 16
#define DHEAD 64
#define MROWS (BATCH*SEQ)   /* 4096 */
#define FLD 68              /* padded smem row length for flash tiles */

// Scratch (allocation-free): 4 x 16 MB fp32 buffers
__device__ float g_qw[MROWS*DMODEL];
__device__ float g_kw[MROWS*DMODEL];
__device__ float g_vw[MROWS*DMODEL];
__device__ float g_att[MROWS*DMODEL];

// ---------------------------------------------------------------------------
// C[m,n] = sum_k A[m,k] * W[n,k] + bias[n]   (torch Linear: y = x @ W.T + b)
// 128x128 block tile, BK=16, 256 threads, 8x8 per-thread microtile.
// ---------------------------------------------------------------------------
__global__ __launch_bounds__(256) void sgemm_bias(
    const float* __restrict__ A, const float* __restrict__ W,
    const float* __restrict__ bias, float* __restrict__ C,
    int M, int N, int K)
{
    __shared__ float As[16][132];
    __shared__ float Bs[16][132];

    const int tid = threadIdx.x;
    const int bm = blockIdx.y * 128;
    const int bn = blockIdx.x * 128;
    const int tx = tid & 15;       // 0..15
    const int ty = tid >> 4;       // 0..15
    const int lr = tid >> 2;       // 0..63 : row within tile (and +64)
    const int lc = (tid & 3) * 4;  // 0,4,8,12 : k-offset within BK

    float acc[8][8];
    #pragma unroll
    for (int i = 0; i < 8; i++)
        #pragma unroll
        for (int j = 0; j < 8; j++) acc[i][j] = 0.0f;

    const float* Ag = A + (size_t)(bm + lr) * K + lc;
    const float* Wg = W + (size_t)(bn + lr) * K + lc;

    for (int k0 = 0; k0 < K; k0 += 16) {
        #pragma unroll
        for (int i = 0; i < 2; i++) {
            float4 a = *(const float4*)(Ag + (size_t)i * 64 * K + k0);
            As[lc+0][lr + i*64] = a.x;
            As[lc+1][lr + i*64] = a.y;
            As[lc+2][lr + i*64] = a.z;
            As[lc+3][lr + i*64] = a.w;
            float4 w = *(const float4*)(Wg + (size_t)i * 64 * K + k0);
            Bs[lc+0][lr + i*64] = w.x;
            Bs[lc+1][lr + i*64] = w.y;
            Bs[lc+2][lr + i*64] = w.z;
            Bs[lc+3][lr + i*64] = w.w;
        }
        __syncthreads();

        #pragma unroll
        for (int kk = 0; kk < 16; kk++) {
            float ra[8], rb[8];
            *(float4*)(ra)     = *(const float4*)&As[kk][ty*8];
            *(float4*)(ra + 4) = *(const float4*)&As[kk][ty*8 + 4];
            *(float4*)(rb)     = *(const float4*)&Bs[kk][tx*8];
            *(float4*)(rb + 4) = *(const float4*)&Bs[kk][tx*8 + 4];
            #pragma unroll
            for (int i = 0; i < 8; i++)
                #pragma unroll
                for (int j = 0; j < 8; j++)
                    acc[i][j] = fmaf(ra[i], rb[j], acc[i][j]);
        }
        __syncthreads();
    }

    // Epilogue: add bias, vectorized stores
    #pragma unroll
    for (int i = 0; i < 8; i++) {
        const int m = bm + ty*8 + i;
        float* Crow = C + (size_t)m * N + bn + tx*8;
        const float* brow = bias + bn + tx*8;
        float4 o0, o1;
        o0.x = acc[i][0] + brow[0];
        o0.y = acc[i][1] + brow[1];
        o0.z = acc[i][2] + brow[2];
        o0.w = acc[i][3] + brow[3];
        o1.x = acc[i][4] + brow[4];
        o1.y = acc[i][5] + brow[5];
        o1.z = acc[i][6] + brow[6];
        o1.w = acc[i][7] + brow[7];
        *(float4*)(Crow)     = o0;
        *(float4*)(Crow + 4) = o1;
    }
}

// ---------------------------------------------------------------------------
// Flash attention (fp32, causal). One block = (batch b, head h, 64-query tile).
// Q/K staged d-major (Qt[d][i]) for conflict-free float4 microloads.
// scale = 1/sqrt(D_MODEL) = 1/32 (faithful to reference).
// ---------------------------------------------------------------------------
__global__ __launch_bounds__(256) void flash_attn(
    const float* __restrict__ Q, const float* __restrict__ K,
    const float* __restrict__ V, float* __restrict__ O)
{
    extern __shared__ __align__(16) float sm[];
    float* Qt = sm;                 // [64][FLD]  d-major
    float* Kt = Qt + 64*FLD;        // [64][FLD]  d-major
    float* Vs = Kt + 64*FLD;        // [64][FLD]  row-major (j, dv)
    float* Ps = Vs + 64*FLD;        // [64][FLD]  row-major (i, j)

    const int qt  = blockIdx.x;     // 0..31
    const int h   = blockIdx.y;     // 0..15
    const int b   = blockIdx.z;     // 0..1
    const int tid = threadIdx.x;
    const int tx  = tid & 15;
    const int ty  = tid >> 4;
    const int qBase = qt * 64;

    const float* Qg  = Q + ((size_t)b * SEQ + qBase) * DMODEL + h * DHEAD;
    const float* Kg0 = K + ((size_t)b * SEQ) * DMODEL + h * DHEAD;
    const float* Vg0 = V + ((size_t)b * SEQ) * DMODEL + h * DHEAD;
    float*       Og  = O + ((size_t)b * SEQ + qBase) * DMODEL + h * DHEAD;

    // Load Q tile transposed: Qt[d][i]
    {
        const int i = tid & 63;
        const int g = tid >> 6;  // 0..3
        #pragma unroll
        for (int c = 0; c < 4; c++) {
            const int d = (g + c*4) * 4;
            float4 v4 = *(const float4*)(Qg + (size_t)i * DMODEL + d);
            Qt[(d+0)*FLD + i] = v4.x;
            Qt[(d+1)*FLD + i] = v4.y;
            Qt[(d+2)*FLD + i] = v4.z;
            Qt[(d+3)*FLD + i] = v4.w;
        }
    }

    float m[4], l[4], o[4][4];
    #pragma unroll
    for (int r = 0; r < 4; r++) {
        m[r] = -1e30f; l[r] = 0.0f;
        #pragma unroll
        for (int c = 0; c < 4; c++) o[r][c] = 0.0f;
    }

    const float scale = 0.03125f;   // 1/32

    for (int kt = 0; kt <= qt; kt++) {
        const int kBase = kt * 64;
        __syncthreads();   // previous iteration done with Kt/Vs/Ps
        {
            const int j = tid & 63;
            const int g = tid >> 6;
            #pragma unroll
            for (int c = 0; c < 4; c++) {
                const int d = (g + c*4) * 4;
                float4 k4 = *(const float4*)(Kg0 + (size_t)(kBase + j) * DMODEL + d);
                Kt[(d+0)*FLD + j] = k4.x;
                Kt[(d+1)*FLD + j] = k4.y;
                Kt[(d+2)*FLD + j] = k4.z;
                Kt[(d+3)*FLD + j] = k4.w;
                float4 v4 = *(const float4*)(Vg0 + (size_t)(kBase + j) * DMODEL + d);
                *(float4*)&Vs[j*FLD + d] = v4;
            }
        }
        __syncthreads();

        // S = Q @ K^T  (4x4 microtile per thread)
        float s[4][4];
        #pragma unroll
        for (int r = 0; r < 4; r++)
            #pragma unroll
            for (int c = 0; c < 4; c++) s[r][c] = 0.0f;

        #pragma unroll 4
        for (int d = 0; d < 64; d++) {
            float rq[4], rk[4];
            *(float4*)rq = *(const float4*)&Qt[d*FLD + ty*4];
            *(float4*)rk = *(const float4*)&Kt[d*FLD + tx*4];
            #pragma unroll
            for (int r = 0; r < 4; r++)
                #pragma unroll
                for (int c = 0; c < 4; c++)
                    s[r][c] = fmaf(rq[r], rk[c], s[r][c]);
        }

        // Online softmax per row
        const bool diag = (kt == qt);
        #pragma unroll
        for (int r = 0; r < 4; r++) {
            const int qi = ty*4 + r;          // local query index
            float mt = -1e30f;
            #pragma unroll
            for (int c = 0; c < 4; c++) {
                const int kj = tx*4 + c;      // local key index
                float val = s[r][c] * scale;
                if (diag && kj > qi) val = -1e30f;
                s[r][c] = val;
                mt = fmaxf(mt, val);
            }
            #pragma unroll
            for (int off = 8; off; off >>= 1)
                mt = fmaxf(mt, __shfl_xor_sync(0xffffffffu, mt, off, 16));
            const float mn = fmaxf(m[r], mt);
            const float alpha = __expf(m[r] - mn);
            m[r] = mn;
            float ls = 0.0f;
            #pragma unroll
            for (int c = 0; c < 4; c++) {
                const float p = __expf(s[r][c] - mn);
                s[r][c] = p;
                ls += p;
            }
            #pragma unroll
            for (int off = 8; off; off >>= 1)
                ls += __shfl_xor_sync(0xffffffffu, ls, off, 16);
            l[r] = l[r] * alpha + ls;
            #pragma unroll
            for (int c = 0; c < 4; c++) o[r][c] *= alpha;
            *(float4*)&Ps[(ty*4 + r)*FLD + tx*4] =
                make_float4(s[r][0], s[r][1], s[r][2], s[r][3]);
        }
        __syncthreads();

        // O += P @ V
        #pragma unroll 4
        for (int j = 0; j < 64; j++) {
            float rv[4];
            *(float4*)rv = *(const float4*)&Vs[j*FLD + tx*4];
            #pragma unroll
            for (int r = 0; r < 4; r++) {
                const float p = Ps[(ty*4 + r)*FLD + j];
                #pragma unroll
                for (int c = 0; c < 4; c++)
                    o[r][c] = fmaf(p, rv[c], o[r][c]);
            }
        }
    }

    // Normalize and write out
    #pragma unroll
    for (int r = 0; r < 4; r++) {
        const float inv = 1.0f / l[r];
        float4 out4 = make_float4(o[r][0]*inv, o[r][1]*inv, o[r][2]*inv, o[r][3]*inv);
        *(float4*)(Og + (size_t)(ty*4 + r) * DMODEL + tx*4) = out4;
    }
}

// ---------------------------------------------------------------------------
extern "C" void kernel_launch(void* const* d_in, const int* in_sizes, int n_in,
                              void* d_out, int out_size)
{
    const float* q  = (const float*)d_in[0];
    const float* k  = (const float*)d_in[1];
    const float* v  = (const float*)d_in[2];
    const float* Wq = (const float*)d_in[3];
    const float* bq = (const float*)d_in[4];
    const float* Wk = (const float*)d_in[5];
    const float* bk = (const float*)d_in[6];
    const float* Wv = (const float*)d_in[7];
    const float* bv = (const float*)d_in[8];
    const float* Wo = (const float*)d_in[9];
    const float* bo = (const float*)d_in[10];
    float* out = (float*)d_out;

    float *qw, *kw, *vw, *att;
    cudaGetSymbolAddress((void**)&qw,  g_qw);
    cudaGetSymbolAddress((void**)&kw,  g_kw);
    cudaGetSymbolAddress((void**)&vw,  g_vw);
    cudaGetSymbolAddress((void**)&att, g_att);

    const int smemFlash = 4 * 64 * FLD * sizeof(float);  // 69632 B
    cudaFuncSetAttribute(flash_attn,
                         cudaFuncAttributeMaxDynamicSharedMemorySize, smemFlash);

    dim3 gGemm(DMODEL/128, MROWS/128);   // (8, 32)
    sgemm_bias<<<gGemm, 256>>>(q, Wq, bq, qw, MROWS, DMODEL, DMODEL);
    sgemm_bias<<<gGemm, 256>>>(k, Wk, bk, kw, MROWS, DMODEL, DMODEL);
    sgemm_bias<<<gGemm, 256>>>(v, Wv, bv, vw, MROWS, DMODEL, DMODEL);

    flash_attn<<<dim3(SEQ/64, NHEAD, BATCH), 256, smemFlash>>>(qw, kw, vw, att);

    sgemm_bias<<<gGemm, 256>>>(att, Wo, bo, out, MROWS, DMODEL, DMODEL);
}

// round 2
// speedup vs baseline: 1.1574x; 1.1574x over previous
#include <cuda_runtime.h>
#include <math.h>

#define BATCH 2
#define SEQ 2048
#define DMODEL 1024
#define NHEAD 16
#define DHEAD 64
#define MROWS (BATCH*SEQ)   /* 4096 */

#define QTILE 128
#define KTILE 64
#define QPITCH 132          /* 132*4 bytes, 16B aligned rows */
#define KPITCH 68           /* 68*4 bytes, 16B aligned rows */

// Scratch (allocation-free): 4 x 16 MB fp32 buffers
__device__ float g_qw[MROWS*DMODEL];
__device__ float g_kw[MROWS*DMODEL];
__device__ float g_vw[MROWS*DMODEL];
__device__ float g_att[MROWS*DMODEL];

// ---------------------------------------------------------------------------
// C[m,n] = sum_k A[m,k] * W[n,k] + bias[n]   (torch Linear: y = x @ W.T + b)
// 128x128 block tile, BK=16, 256 threads, 8x8 microtile, double-buffered smem.
// ---------------------------------------------------------------------------
__global__ __launch_bounds__(256) void sgemm_bias(
    const float* __restrict__ A, const float* __restrict__ W,
    const float* __restrict__ bias, float* __restrict__ C,
    int M, int N, int K)
{
    __shared__ float As[2][16][132];
    __shared__ float Bs[2][16][132];

    const int tid = threadIdx.x;
    const int bm = blockIdx.y * 128;
    const int bn = blockIdx.x * 128;
    const int tx = tid & 15;       // 0..15
    const int ty = tid >> 4;       // 0..15
    const int lr = tid >> 2;       // 0..63 : row within tile (and +64)
    const int lc = (tid & 3) * 4;  // 0,4,8,12 : k-offset within BK

    float acc[8][8];
    #pragma unroll
    for (int i = 0; i < 8; i++)
        #pragma unroll
        for (int j = 0; j < 8; j++) acc[i][j] = 0.0f;

    const float* Ag = A + (size_t)(bm + lr) * K + lc;
    const float* Wg = W + (size_t)(bn + lr) * K + lc;

    // preload k-block 0
    float4 pa[2], pw[2];
    #pragma unroll
    for (int i = 0; i < 2; i++) {
        pa[i] = *(const float4*)(Ag + (size_t)i * 64 * K);
        pw[i] = *(const float4*)(Wg + (size_t)i * 64 * K);
    }
    #pragma unroll
    for (int i = 0; i < 2; i++) {
        As[0][lc+0][lr + i*64] = pa[i].x;
        As[0][lc+1][lr + i*64] = pa[i].y;
        As[0][lc+2][lr + i*64] = pa[i].z;
        As[0][lc+3][lr + i*64] = pa[i].w;
        Bs[0][lc+0][lr + i*64] = pw[i].x;
        Bs[0][lc+1][lr + i*64] = pw[i].y;
        Bs[0][lc+2][lr + i*64] = pw[i].z;
        Bs[0][lc+3][lr + i*64] = pw[i].w;
    }
    __syncthreads();

    int buf = 0;
    for (int k0 = 0; k0 < K; k0 += 16) {
        const bool hasNext = (k0 + 16 < K);
        if (hasNext) {
            #pragma unroll
            for (int i = 0; i < 2; i++) {
                pa[i] = *(const float4*)(Ag + (size_t)i * 64 * K + k0 + 16);
                pw[i] = *(const float4*)(Wg + (size_t)i * 64 * K + k0 + 16);
            }
        }

        #pragma unroll
        for (int kk = 0; kk < 16; kk++) {
            float ra[8], rb[8];
            *(float4*)(ra)     = *(const float4*)&As[buf][kk][ty*8];
            *(float4*)(ra + 4) = *(const float4*)&As[buf][kk][ty*8 + 4];
            *(float4*)(rb)     = *(const float4*)&Bs[buf][kk][tx*8];
            *(float4*)(rb + 4) = *(const float4*)&Bs[buf][kk][tx*8 + 4];
            #pragma unroll
            for (int i = 0; i < 8; i++)
                #pragma unroll
                for (int j = 0; j < 8; j++)
                    acc[i][j] = fmaf(ra[i], rb[j], acc[i][j]);
        }

        if (hasNext) {
            const int nb = buf ^ 1;
            #pragma unroll
            for (int i = 0; i < 2; i++) {
                As[nb][lc+0][lr + i*64] = pa[i].x;
                As[nb][lc+1][lr + i*64] = pa[i].y;
                As[nb][lc+2][lr + i*64] = pa[i].z;
                As[nb][lc+3][lr + i*64] = pa[i].w;
                Bs[nb][lc+0][lr + i*64] = pw[i].x;
                Bs[nb][lc+1][lr + i*64] = pw[i].y;
                Bs[nb][lc+2][lr + i*64] = pw[i].z;
                Bs[nb][lc+3][lr + i*64] = pw[i].w;
            }
            __syncthreads();
        }
        buf ^= 1;
    }

    // Epilogue: add bias, vectorized stores
    #pragma unroll
    for (int i = 0; i < 8; i++) {
        const int m = bm + ty*8 + i;
        float* Crow = C + (size_t)m * N + bn + tx*8;
        const float* brow = bias + bn + tx*8;
        float4 o0, o1;
        o0.x = acc[i][0] + brow[0];
        o0.y = acc[i][1] + brow[1];
        o0.z = acc[i][2] + brow[2];
        o0.w = acc[i][3] + brow[3];
        o1.x = acc[i][4] + brow[4];
        o1.y = acc[i][5] + brow[5];
        o1.z = acc[i][6] + brow[6];
        o1.w = acc[i][7] + brow[7];
        *(float4*)(Crow)     = o0;
        *(float4*)(Crow + 4) = o1;
    }
}

// ---------------------------------------------------------------------------
// Flash attention (fp32, causal). Block = (b, h, 128-query tile), 64-key tiles.
// 256 threads = 16(tx: key cols /4) x 16(ty: query rows /8), 8x4 microtile.
// Q/K staged d-major for conflict-free float4 microloads; P read back as
// float4 rows (broadcast across tx -> conflict-free).
// scale = 1/sqrt(D_MODEL) = 1/32 folded into Q at load.
// ---------------------------------------------------------------------------
__global__ __launch_bounds__(256, 2) void flash_attn(
    const float* __restrict__ Q, const float* __restrict__ K,
    const float* __restrict__ V, float* __restrict__ O)
{
    extern __shared__ __align__(16) float sm[];
    float* Qt = sm;                     // [64][QPITCH]  d-major (d, i)
    float* Kt = Qt + 64*QPITCH;         // [64][KPITCH]  d-major (d, j)
    float* Vs = Kt + 64*KPITCH;         // [64][KPITCH]  row-major (j, d)
    float* Ps = Vs + 64*KPITCH;         // [128][KPITCH] row-major (i, j)

    const int qt  = blockIdx.x;         // 0..15
    const int h   = blockIdx.y;         // 0..15
    const int b   = blockIdx.z;         // 0..1
    const int tid = threadIdx.x;
    const int tx  = tid & 15;
    const int ty  = tid >> 4;
    const int qBase = qt * QTILE;

    const float* Qg  = Q + ((size_t)b * SEQ + qBase) * DMODEL + h * DHEAD;
    const float* Kg0 = K + ((size_t)b * SEQ) * DMODEL + h * DHEAD;
    const float* Vg0 = V + ((size_t)b * SEQ) * DMODEL + h * DHEAD;
    float*       Og  = O + ((size_t)b * SEQ + qBase) * DMODEL + h * DHEAD;

    const float scale = 0.03125f;   // 1/32

    // Load Q tile transposed (d-major), folding in the softmax scale.
    #pragma unroll
    for (int i0 = 0; i0 < QTILE; i0 += 16) {
        const int i = i0 + ty;
        float4 v4 = *(const float4*)(Qg + (size_t)i * DMODEL + tx*4);
        Qt[(tx*4+0)*QPITCH + i] = v4.x * scale;
        Qt[(tx*4+1)*QPITCH + i] = v4.y * scale;
        Qt[(tx*4+2)*QPITCH + i] = v4.z * scale;
        Qt[(tx*4+3)*QPITCH + i] = v4.w * scale;
    }

    float m[8], l[8], o[8][4];
    #pragma unroll
    for (int r = 0; r < 8; r++) {
        m[r] = -1e30f; l[r] = 0.0f;
        #pragma unroll
        for (int c = 0; c < 4; c++) o[r][c] = 0.0f;
    }

    const int ktMax = 2*qt + 1;
    for (int kt = 0; kt <= ktMax; kt++) {
        const int kBase = kt * KTILE;
        __syncthreads();   // previous iteration done with Kt/Vs/Ps

        // Load K (transposed) and V tiles
        #pragma unroll
        for (int j0 = 0; j0 < KTILE; j0 += 16) {
            const int j = j0 + ty;
            float4 k4 = *(const float4*)(Kg0 + (size_t)(kBase + j) * DMODEL + tx*4);
            Kt[(tx*4+0)*KPITCH + j] = k4.x;
            Kt[(tx*4+1)*KPITCH + j] = k4.y;
            Kt[(tx*4+2)*KPITCH + j] = k4.z;
            Kt[(tx*4+3)*KPITCH + j] = k4.w;
            float4 v4 = *(const float4*)(Vg0 + (size_t)(kBase + j) * DMODEL + tx*4);
            *(float4*)&Vs[j*KPITCH + tx*4] = v4;
        }
        __syncthreads();

        // S = Qs @ K^T  (8x4 microtile per thread; Q already scaled)
        float s[8][4];
        #pragma unroll
        for (int r = 0; r < 8; r++)
            #pragma unroll
            for (int c = 0; c < 4; c++) s[r][c] = 0.0f;

        #pragma unroll 4
        for (int d = 0; d < 64; d++) {
            float rq[8], rk[4];
            *(float4*)(rq)     = *(const float4*)&Qt[d*QPITCH + ty*8];
            *(float4*)(rq + 4) = *(const float4*)&Qt[d*QPITCH + ty*8 + 4];
            *(float4*)(rk)     = *(const float4*)&Kt[d*KPITCH + tx*4];
            #pragma unroll
            for (int r = 0; r < 8; r++)
                #pragma unroll
                for (int c = 0; c < 4; c++)
                    s[r][c] = fmaf(rq[r], rk[c], s[r][c]);
        }

        // Online softmax per row (16-lane row groups)
        const bool needMask = (kt >= 2*qt);
        const int koff = kBase - qBase;     // key_global - query_base
        #pragma unroll
        for (int r = 0; r < 8; r++) {
            const int qi = ty*8 + r;        // local query index
            float mt = -1e30f;
            #pragma unroll
            for (int c = 0; c < 4; c++) {
                float val = s[r][c];
                const int kj = tx*4 + c;
                if (needMask && (kj + koff > qi)) val = -1e30f;
                s[r][c] = val;
                mt = fmaxf(mt, val);
            }
            #pragma unroll
            for (int off = 8; off; off >>= 1)
                mt = fmaxf(mt, __shfl_xor_sync(0xffffffffu, mt, off, 16));
            const float mn = fmaxf(m[r], mt);
            const float alpha = __expf(m[r] - mn);
            m[r] = mn;
            float ls = 0.0f;
            #pragma unroll
            for (int c = 0; c < 4; c++) {
                const float p = __expf(s[r][c] - mn);
                s[r][c] = p;
                ls += p;
            }
            #pragma unroll
            for (int off = 8; off; off >>= 1)
                ls += __shfl_xor_sync(0xffffffffu, ls, off, 16);
            l[r] = l[r] * alpha + ls;
            #pragma unroll
            for (int c = 0; c < 4; c++) o[r][c] *= alpha;
            *(float4*)&Ps[(ty*8 + r)*KPITCH + tx*4] =
                make_float4(s[r][0], s[r][1], s[r][2], s[r][3]);
        }
        __syncthreads();

        // O += P @ V : P rows read as float4 (broadcast), V contiguous float4
        #pragma unroll 2
        for (int j0 = 0; j0 < KTILE; j0 += 4) {
            float rv[4][4];
            #pragma unroll
            for (int jj = 0; jj < 4; jj++)
                *(float4*)rv[jj] = *(const float4*)&Vs[(j0+jj)*KPITCH + tx*4];
            #pragma unroll
            for (int r = 0; r < 8; r++) {
                float rp[4];
                *(float4*)rp = *(const float4*)&Ps[(ty*8 + r)*KPITCH + j0];
                #pragma unroll
                for (int c = 0; c < 4; c++) {
                    o[r][c] = fmaf(rp[0], rv[0][c], o[r][c]);
                    o[r][c] = fmaf(rp[1], rv[1][c], o[r][c]);
                    o[r][c] = fmaf(rp[2], rv[2][c], o[r][c]);
                    o[r][c] = fmaf(rp[3], rv[3][c], o[r][c]);
                }
            }
        }
    }

    // Normalize and write out
    #pragma unroll
    for (int r = 0; r < 8; r++) {
        const float inv = 1.0f / l[r];
        float4 out4 = make_float4(o[r][0]*inv, o[r][1]*inv, o[r][2]*inv, o[r][3]*inv);
        *(float4*)(Og + (size_t)(ty*8 + r) * DMODEL + tx*4) = out4;
    }
}

// ---------------------------------------------------------------------------
extern "C" void kernel_launch(void* const* d_in, const int* in_sizes, int n_in,
                              void* d_out, int out_size)
{
    const float* q  = (const float*)d_in[0];
    const float* k  = (const float*)d_in[1];
    const float* v  = (const float*)d_in[2];
    const float* Wq = (const float*)d_in[3];
    const float* bq = (const float*)d_in[4];
    const float* Wk = (const float*)d_in[5];
    const float* bk = (const float*)d_in[6];
    const float* Wv = (const float*)d_in[7];
    const float* bv = (const float*)d_in[8];
    const float* Wo = (const float*)d_in[9];
    const float* bo = (const float*)d_in[10];
    float* out = (float*)d_out;

    float *qw, *kw, *vw, *att;
    cudaGetSymbolAddress((void**)&qw,  g_qw);
    cudaGetSymbolAddress((void**)&kw,  g_kw);
    cudaGetSymbolAddress((void**)&vw,  g_vw);
    cudaGetSymbolAddress((void**)&att, g_att);

    const int smemFlash = (64*QPITCH + 64*KPITCH + 64*KPITCH + 128*KPITCH)
                          * (int)sizeof(float);  // 103424 B
    cudaFuncSetAttribute(flash_attn,
                         cudaFuncAttributeMaxDynamicSharedMemorySize, smemFlash);

    dim3 gGemm(DMODEL/128, MROWS/128);   // (8, 32)
    sgemm_bias<<<gGemm, 256>>>(q, Wq, bq, qw, MROWS, DMODEL, DMODEL);
    sgemm_bias<<<gGemm, 256>>>(k, Wk, bk, kw, MROWS, DMODEL, DMODEL);
    sgemm_bias<<<gGemm, 256>>>(v, Wv, bv, vw, MROWS, DMODEL, DMODEL);

    flash_attn<<<dim3(SEQ/QTILE, NHEAD, BATCH), 256, smemFlash>>>(qw, kw, vw, att);

    sgemm_bias<<<gGemm, 256>>>(att, Wo, bo, out, MROWS, DMODEL, DMODEL);
}

// round 3
// speedup vs baseline: 2.1372x; 1.8466x over previous
#include <cuda_runtime.h>
#include <math.h>

#define BATCH 2
#define SEQ 2048
#define DMODEL 1024
#define NHEAD 16
#define DHEAD 64
#define MROWS (BATCH*SEQ)   /* 4096 */

// Scratch (allocation-free)
__device__ float g_qw[MROWS*DMODEL];
__device__ float g_kw[MROWS*DMODEL];
__device__ float g_vw[MROWS*DMODEL];
__device__ float g_att[MROWS*DMODEL];

// ---------------------------------------------------------------------------
// TF32 helpers
// ---------------------------------------------------------------------------
__device__ __forceinline__ unsigned f2tf(float x) {
    unsigned r;
    asm("cvt.rna.tf32.f32 %0, %1;" : "=r"(r) : "f"(x));
    return r;
}

__device__ __forceinline__ void mma8(float* d, const unsigned* a,
                                     unsigned b0, unsigned b1) {
    asm volatile(
        "mma.sync.aligned.m16n8k8.row.col.f32.tf32.tf32.f32 "
        "{%0,%1,%2,%3}, {%4,%5,%6,%7}, {%8,%9}, {%0,%1,%2,%3};"
        : "+f"(d[0]), "+f"(d[1]), "+f"(d[2]), "+f"(d[3])
        : "r"(a[0]), "r"(a[1]), "r"(a[2]), "r"(a[3]), "r"(b0), "r"(b1));
}

// ---------------------------------------------------------------------------
// C[m,n] = sum_k A[m,k]*W[n,k] + bias[n], M=4096-ish tile grid, N=K=1024.
// 128x128 CTA tile, BK=16 double buffered, 8 warps (2 M x 4 N),
// each warp 64x32 via 4x4 m16n8k8 tf32 fragments.
// ---------------------------------------------------------------------------
#define GP 20   /* smem pitch in words for BK=16 (+4 pad): (4r+k)%32 distinct */

__device__ __forceinline__ void gemm_body(
    const float* __restrict__ A, const float* __restrict__ W,
    const float* __restrict__ bias, float* __restrict__ C)
{
    __shared__ unsigned As[2][128*GP];
    __shared__ unsigned Ws[2][128*GP];

    const int K = DMODEL, N = DMODEL;
    const int tid  = threadIdx.x;
    const int lane = tid & 31;
    const int wid  = tid >> 5;
    const int bm = blockIdx.y * 128;
    const int bn = blockIdx.x * 128;
    const int wm = (wid & 1) * 64;
    const int wn = (wid >> 1) * 32;

    const int srow = tid & 127;
    const int svar = tid >> 7;           // 0..1

    const float* Arow = A + (size_t)(bm + srow) * K;
    const float* Wrow = W + (size_t)(bn + srow) * K;

    float acc[4][4][4];
    #pragma unroll
    for (int i = 0; i < 4; i++)
        #pragma unroll
        for (int j = 0; j < 4; j++)
            #pragma unroll
            for (int e = 0; e < 4; e++) acc[i][j][e] = 0.0f;

    float4 pa[2], pw[2];
    // prefetch tile 0
    #pragma unroll
    for (int v = 0; v < 2; v++) {
        const int c4 = ((svar + 2*v) & 3) * 4;
        pa[v] = *(const float4*)(Arow + c4);
        pw[v] = *(const float4*)(Wrow + c4);
    }
    #pragma unroll
    for (int v = 0; v < 2; v++) {
        const int c4 = ((svar + 2*v) & 3) * 4;
        *(uint4*)&As[0][srow*GP + c4] =
            make_uint4(f2tf(pa[v].x), f2tf(pa[v].y), f2tf(pa[v].z), f2tf(pa[v].w));
        *(uint4*)&Ws[0][srow*GP + c4] =
            make_uint4(f2tf(pw[v].x), f2tf(pw[v].y), f2tf(pw[v].z), f2tf(pw[v].w));
    }
    __syncthreads();

    const int ntiles = K / 16;           // 64
    for (int kt = 0; kt < ntiles; kt++) {
        const int cur = kt & 1;
        if (kt + 1 < ntiles) {
            const int k0 = (kt + 1) * 16;
            #pragma unroll
            for (int v = 0; v < 2; v++) {
                const int c4 = ((svar + 2*v) & 3) * 4;
                pa[v] = *(const float4*)(Arow + k0 + c4);
                pw[v] = *(const float4*)(Wrow + k0 + c4);
            }
        }

        #pragma unroll
        for (int kk = 0; kk < 2; kk++) {
            unsigned af[4][4];
            #pragma unroll
            for (int mf = 0; mf < 4; mf++) {
                const int base = (wm + mf*16 + (lane>>2))*GP + kk*8 + (lane&3);
                af[mf][0] = As[cur][base];
                af[mf][1] = As[cur][base + 8*GP];
                af[mf][2] = As[cur][base + 4];
                af[mf][3] = As[cur][base + 8*GP + 4];
            }
            #pragma unroll
            for (int nf = 0; nf < 4; nf++) {
                const int bb = (wn + nf*8 + (lane>>2))*GP + kk*8 + (lane&3);
                const unsigned b0 = Ws[cur][bb];
                const unsigned b1 = Ws[cur][bb + 4];
                #pragma unroll
                for (int mf = 0; mf < 4; mf++)
                    mma8(acc[mf][nf], af[mf], b0, b1);
            }
        }

        if (kt + 1 < ntiles) {
            const int nb = cur ^ 1;
            #pragma unroll
            for (int v = 0; v < 2; v++) {
                const int c4 = ((svar + 2*v) & 3) * 4;
                *(uint4*)&As[nb][srow*GP + c4] =
                    make_uint4(f2tf(pa[v].x), f2tf(pa[v].y), f2tf(pa[v].z), f2tf(pa[v].w));
                *(uint4*)&Ws[nb][srow*GP + c4] =
                    make_uint4(f2tf(pw[v].x), f2tf(pw[v].y), f2tf(pw[v].z), f2tf(pw[v].w));
            }
            __syncthreads();
        }
    }

    // Epilogue
    #pragma unroll
    for (int mf = 0; mf < 4; mf++) {
        const int m0 = bm + wm + mf*16 + (lane>>2);
        #pragma unroll
        for (int nf = 0; nf < 4; nf++) {
            const int n0 = bn + wn + nf*8 + 2*(lane&3);
            const float2 bv = *(const float2*)(bias + n0);
            *(float2*)(C + (size_t)m0 * N + n0) =
                make_float2(acc[mf][nf][0] + bv.x, acc[mf][nf][1] + bv.y);
            *(float2*)(C + (size_t)(m0+8) * N + n0) =
                make_float2(acc[mf][nf][2] + bv.x, acc[mf][nf][3] + bv.y);
        }
    }
}

__global__ __launch_bounds__(256, 2) void gemm_tf32(
    const float* __restrict__ A, const float* __restrict__ W,
    const float* __restrict__ bias, float* __restrict__ C)
{
    gemm_body(A, W, bias, C);
}

__global__ __launch_bounds__(256, 2) void gemm_qkv(
    const float* __restrict__ q, const float* __restrict__ k,
    const float* __restrict__ v,
    const float* __restrict__ Wq, const float* __restrict__ bq,
    const float* __restrict__ Wk, const float* __restrict__ bk,
    const float* __restrict__ Wv, const float* __restrict__ bv,
    float* __restrict__ oq, float* __restrict__ ok, float* __restrict__ ov)
{
    const float* A; const float* W; const float* bias; float* C;
    if (blockIdx.z == 0)      { A = q; W = Wq; bias = bq; C = oq; }
    else if (blockIdx.z == 1) { A = k; W = Wk; bias = bk; C = ok; }
    else                      { A = v; W = Wv; bias = bv; C = ov; }
    gemm_body(A, W, bias, C);
}

// ---------------------------------------------------------------------------
// Flash attention with tf32 mma. CTA = (b, h, 128-query tile); 64-key tiles.
// 8 warps, each owns 16 query rows. S and PV both via m16n8k8 tf32.
// scale = 1/32 folded into Q (exact power of two).
// ---------------------------------------------------------------------------
#define FP 68   /* smem pitch words: (4r+c)%32 distinct for fragment loads */

__global__ __launch_bounds__(256, 2) void flash_mma(
    const float* __restrict__ Q, const float* __restrict__ K,
    const float* __restrict__ V, float* __restrict__ O)
{
    extern __shared__ unsigned sm[];
    unsigned* Qs = sm;                // [128][FP]  (i, d)  tf32, pre-scaled
    unsigned* Ks = Qs + 128*FP;       // [64][FP]   (j, d)  tf32
    unsigned* Vt = Ks + 64*FP;        // [64][FP]   (d, j)  tf32 (transposed)
    unsigned* Ps = Vt + 64*FP;        // [128][FP]  (i, j)  tf32

    const int qt = gridDim.x - 1 - blockIdx.x;   // big tiles first
    const int h  = blockIdx.y;
    const int b  = blockIdx.z;
    const int tid  = threadIdx.x;
    const int lane = tid & 31;
    const int wid  = tid >> 5;
    const int tx = tid & 15;
    const int ty = tid >> 4;
    const int qBase = qt * 128;

    const float* Qg  = Q + ((size_t)b * SEQ + qBase) * DMODEL + h * DHEAD;
    const float* Kg0 = K + ((size_t)b * SEQ) * DMODEL + h * DHEAD;
    const float* Vg0 = V + ((size_t)b * SEQ) * DMODEL + h * DHEAD;

    const float scale = 0.03125f;

    // Stage Q (scaled, tf32)
    #pragma unroll
    for (int i0 = 0; i0 < 128; i0 += 16) {
        const int i = i0 + ty;
        float4 v4 = *(const float4*)(Qg + (size_t)i * DMODEL + tx*4);
        *(uint4*)&Qs[i*FP + tx*4] = make_uint4(
            f2tf(v4.x*scale), f2tf(v4.y*scale), f2tf(v4.z*scale), f2tf(v4.w*scale));
    }

    const int r0 = (wid << 4) + (lane >> 2);  // warp-local query row (and +8)
    const int qi0 = qBase + r0;
    const int qi1 = qi0 + 8;

    float m0 = -1e30f, m1 = -1e30f, l0 = 0.0f, l1 = 0.0f;
    float o[8][4];
    #pragma unroll
    for (int nf = 0; nf < 8; nf++)
        #pragma unroll
        for (int e = 0; e < 4; e++) o[nf][e] = 0.0f;

    const int ktMax = 2*qt + 1;
    for (int kt = 0; kt <= ktMax; kt++) {
        const int kBase = kt * 64;
        __syncthreads();
        // Stage K row-major, V transposed (both tf32)
        #pragma unroll
        for (int j0 = 0; j0 < 64; j0 += 16) {
            const int j = j0 + ty;
            float4 k4 = *(const float4*)(Kg0 + (size_t)(kBase + j) * DMODEL + tx*4);
            *(uint4*)&Ks[j*FP + tx*4] = make_uint4(
                f2tf(k4.x), f2tf(k4.y), f2tf(k4.z), f2tf(k4.w));
            float4 v4 = *(const float4*)(Vg0 + (size_t)(kBase + j) * DMODEL + tx*4);
            Vt[(tx*4+0)*FP + j] = f2tf(v4.x);
            Vt[(tx*4+1)*FP + j] = f2tf(v4.y);
            Vt[(tx*4+2)*FP + j] = f2tf(v4.z);
            Vt[(tx*4+3)*FP + j] = f2tf(v4.w);
        }
        __syncthreads();

        // S = Qs @ Ks^T
        float s[8][4];
        #pragma unroll
        for (int nf = 0; nf < 8; nf++)
            #pragma unroll
            for (int e = 0; e < 4; e++) s[nf][e] = 0.0f;

        #pragma unroll
        for (int k8 = 0; k8 < 8; k8++) {
            unsigned a[4];
            const int base = r0*FP + k8*8 + (lane&3);
            a[0] = Qs[base];
            a[1] = Qs[base + 8*FP];
            a[2] = Qs[base + 4];
            a[3] = Qs[base + 8*FP + 4];
            #pragma unroll
            for (int nf = 0; nf < 8; nf++) {
                const int bb = (nf*8 + (lane>>2))*FP + k8*8 + (lane&3);
                mma8(s[nf], a, Ks[bb], Ks[bb + 4]);
            }
        }

        // Mask + online softmax (rows r0 and r0+8 per thread)
        const bool needMask = (kt >= 2*qt);
        float mt0 = -1e30f, mt1 = -1e30f;
        #pragma unroll
        for (int nf = 0; nf < 8; nf++) {
            #pragma unroll
            for (int e = 0; e < 2; e++) {
                if (needMask) {
                    const int kj = kBase + nf*8 + 2*(lane&3) + e;
                    if (kj > qi0) s[nf][e]   = -1e30f;
                    if (kj > qi1) s[nf][2+e] = -1e30f;
                }
                mt0 = fmaxf(mt0, s[nf][e]);
                mt1 = fmaxf(mt1, s[nf][2+e]);
            }
        }
        mt0 = fmaxf(mt0, __shfl_xor_sync(0xffffffffu, mt0, 1));
        mt0 = fmaxf(mt0, __shfl_xor_sync(0xffffffffu, mt0, 2));
        mt1 = fmaxf(mt1, __shfl_xor_sync(0xffffffffu, mt1, 1));
        mt1 = fmaxf(mt1, __shfl_xor_sync(0xffffffffu, mt1, 2));

        const float mn0 = fmaxf(m0, mt0);
        const float mn1 = fmaxf(m1, mt1);
        const float alpha0 = __expf(m0 - mn0);
        const float alpha1 = __expf(m1 - mn1);
        m0 = mn0; m1 = mn1;

        float ls0 = 0.0f, ls1 = 0.0f;
        #pragma unroll
        for (int nf = 0; nf < 8; nf++) {
            #pragma unroll
            for (int e = 0; e < 2; e++) {
                const float p0 = __expf(s[nf][e]   - mn0);
                const float p1 = __expf(s[nf][2+e] - mn1);
                s[nf][e]   = p0;
                s[nf][2+e] = p1;
                ls0 += p0; ls1 += p1;
            }
        }
        ls0 += __shfl_xor_sync(0xffffffffu, ls0, 1);
        ls0 += __shfl_xor_sync(0xffffffffu, ls0, 2);
        ls1 += __shfl_xor_sync(0xffffffffu, ls1, 1);
        ls1 += __shfl_xor_sync(0xffffffffu, ls1, 2);
        l0 = l0*alpha0 + ls0;
        l1 = l1*alpha1 + ls1;

        #pragma unroll
        for (int nf = 0; nf < 8; nf++) {
            o[nf][0] *= alpha0; o[nf][1] *= alpha0;
            o[nf][2] *= alpha1; o[nf][3] *= alpha1;
        }

        // P -> smem (tf32); warp-local round trip
        __syncwarp();
        #pragma unroll
        for (int nf = 0; nf < 8; nf++) {
            const int col = nf*8 + 2*(lane&3);
            *(uint2*)&Ps[r0*FP + col] =
                make_uint2(f2tf(s[nf][0]), f2tf(s[nf][1]));
            *(uint2*)&Ps[(r0+8)*FP + col] =
                make_uint2(f2tf(s[nf][2]), f2tf(s[nf][3]));
        }
        __syncwarp();

        // O += P @ V   (B = Vt: element (k=j, n=d))
        #pragma unroll
        for (int k8 = 0; k8 < 8; k8++) {
            unsigned a[4];
            const int base = r0*FP + k8*8 + (lane&3);
            a[0] = Ps[base];
            a[1] = Ps[base + 8*FP];
            a[2] = Ps[base + 4];
            a[3] = Ps[base + 8*FP + 4];
            #pragma unroll
            for (int nf = 0; nf < 8; nf++) {
                const int bb = (nf*8 + (lane>>2))*FP + k8*8 + (lane&3);
                mma8(o[nf], a, Vt[bb], Vt[bb + 4]);
            }
        }
    }

    // Normalize + write
    const float inv0 = 1.0f / l0;
    const float inv1 = 1.0f / l1;
    float* Ob = O + (size_t)b * SEQ * DMODEL + (size_t)h * DHEAD;
    #pragma unroll
    for (int nf = 0; nf < 8; nf++) {
        const int n = nf*8 + 2*(lane&3);
        *(float2*)(Ob + (size_t)qi0 * DMODEL + n) =
            make_float2(o[nf][0]*inv0, o[nf][1]*inv0);
        *(float2*)(Ob + (size_t)qi1 * DMODEL + n) =
            make_float2(o[nf][2]*inv1, o[nf][3]*inv1);
    }
}

// ---------------------------------------------------------------------------
extern "C" void kernel_launch(void* const* d_in, const int* in_sizes, int n_in,
                              void* d_out, int out_size)
{
    const float* q  = (const float*)d_in[0];
    const float* k  = (const float*)d_in[1];
    const float* v  = (const float*)d_in[2];
    const float* Wq = (const float*)d_in[3];
    const float* bq = (const float*)d_in[4];
    const float* Wk = (const float*)d_in[5];
    const float* bk = (const float*)d_in[6];
    const float* Wv = (const float*)d_in[7];
    const float* bv = (const float*)d_in[8];
    const float* Wo = (const float*)d_in[9];
    const float* bo = (const float*)d_in[10];
    float* out = (float*)d_out;

    float *qw, *kw, *vw, *att;
    cudaGetSymbolAddress((void**)&qw,  g_qw);
    cudaGetSymbolAddress((void**)&kw,  g_kw);
    cudaGetSymbolAddress((void**)&vw,  g_vw);
    cudaGetSymbolAddress((void**)&att, g_att);

    const int smemFlash = (128*FP + 64*FP + 64*FP + 128*FP) * (int)sizeof(unsigned);
    cudaFuncSetAttribute(flash_mma,
                         cudaFuncAttributeMaxDynamicSharedMemorySize, smemFlash);

    dim3 gQKV(DMODEL/128, MROWS/128, 3);   // (8, 32, 3)
    gemm_qkv<<<gQKV, 256>>>(q, k, v, Wq, bq, Wk, bk, Wv, bv, qw, kw, vw);

    flash_mma<<<dim3(SEQ/128, NHEAD, BATCH), 256, smemFlash>>>(qw, kw, vw, att);

    dim3 gGemm(DMODEL/128, MROWS/128);     // (8, 32)
    gemm_tf32<<<gGemm, 256>>>(att, Wo, bo, out);
}

// round 4
// speedup vs baseline: 3.3061x; 1.5469x over previous
#include <cuda_runtime.h>
#include <math.h>

#define BATCH 2
#define SEQ 2048
#define DMODEL 1024
#define NHEAD 16
#define DHEAD 64
#define MROWS (BATCH*SEQ)   /* 4096 */

// Scratch (allocation-free)
__device__ float g_qw[MROWS*DMODEL];
__device__ float g_kw[MROWS*DMODEL];
__device__ float g_vw[MROWS*DMODEL];
__device__ float g_att[MROWS*DMODEL];

// ---------------------------------------------------------------------------
// Helpers
// ---------------------------------------------------------------------------
__device__ __forceinline__ unsigned f2tf(float x) {
    unsigned r;
    asm("cvt.rna.tf32.f32 %0, %1;" : "=r"(r) : "f"(x));
    return r;
}

__device__ __forceinline__ void mma8(float* d, const unsigned* a,
                                     unsigned b0, unsigned b1) {
    asm volatile(
        "mma.sync.aligned.m16n8k8.row.col.f32.tf32.tf32.f32 "
        "{%0,%1,%2,%3}, {%4,%5,%6,%7}, {%8,%9}, {%0,%1,%2,%3};"
        : "+f"(d[0]), "+f"(d[1]), "+f"(d[2]), "+f"(d[3])
        : "r"(a[0]), "r"(a[1]), "r"(a[2]), "r"(a[3]), "r"(b0), "r"(b1));
}

__device__ __forceinline__ void cp16(const void* smem_dst, const void* gsrc) {
    unsigned d = (unsigned)__cvta_generic_to_shared(smem_dst);
    asm volatile("cp.async.cg.shared.global [%0], [%1], 16;" :: "r"(d), "l"(gsrc));
}
#define CP_COMMIT asm volatile("cp.async.commit_group;")
#define CP_WAIT0  asm volatile("cp.async.wait_group 0;")
#define CP_WAIT1  asm volatile("cp.async.wait_group 1;")

// ---------------------------------------------------------------------------
// GEMM: C[m,n] = sum_k A[m,k]*W[n,k] + bias[n].  N=K=1024.
// CTA 128x128, BK=32 double-buffered via cp.async, 4 warps (2x2) of 64x64.
// Raw f32 in smem; cvt.rna.tf32 applied on fragment registers.
// ---------------------------------------------------------------------------
#define GP 36               /* pitch words (32 + 4 pad): conflict-free frags */
#define GSM (128*GP)

__device__ __forceinline__ void gemm_body(
    const float* __restrict__ A, const float* __restrict__ W,
    const float* __restrict__ bias, float* __restrict__ C, float* sm)
{
    float* As = sm;            // [2][128*GP]
    float* Ws = sm + 2*GSM;    // [2][128*GP]

    const int tid  = threadIdx.x;
    const int lane = tid & 31;
    const int wid  = tid >> 5;           // 0..3
    const int bm = blockIdx.y * 128;
    const int bn = blockIdx.x * 128;
    const int wm = (wid & 1) * 64;
    const int wn = (wid >> 1) * 64;

    const float* Ag = A + (size_t)bm * DMODEL;
    const float* Wg = W + (size_t)bn * DMODEL;

    float acc[4][8][4];
    #pragma unroll
    for (int mf = 0; mf < 4; mf++)
        #pragma unroll
        for (int nf = 0; nf < 8; nf++)
            #pragma unroll
            for (int e = 0; e < 4; e++) acc[mf][nf][e] = 0.0f;

    auto stage = [&](int buf, int k0) {
        #pragma unroll
        for (int i = 0; i < 8; i++) {
            const int idx = i*128 + tid;
            const int row = idx >> 3;
            const int kc  = (idx & 7) * 4;
            cp16(&As[buf*GSM + row*GP + kc], Ag + (size_t)row*DMODEL + k0 + kc);
            cp16(&Ws[buf*GSM + row*GP + kc], Wg + (size_t)row*DMODEL + k0 + kc);
        }
        CP_COMMIT;
    };

    stage(0, 0);

    const int ntiles = DMODEL / 32;      // 32
    for (int kt = 0; kt < ntiles; kt++) {
        const int cur = kt & 1;
        if (kt + 1 < ntiles) {
            stage(cur ^ 1, (kt + 1) * 32);
            CP_WAIT1;
        } else {
            CP_WAIT0;
        }
        __syncthreads();

        const float* Ab = As + cur*GSM;
        const float* Wb = Ws + cur*GSM;
        #pragma unroll
        for (int k8 = 0; k8 < 4; k8++) {
            unsigned af[4][4];
            #pragma unroll
            for (int mf = 0; mf < 4; mf++) {
                const int base = (wm + mf*16 + (lane>>2))*GP + k8*8 + (lane&3);
                af[mf][0] = f2tf(Ab[base]);
                af[mf][1] = f2tf(Ab[base + 8*GP]);
                af[mf][2] = f2tf(Ab[base + 4]);
                af[mf][3] = f2tf(Ab[base + 8*GP + 4]);
            }
            unsigned bf[8][2];
            #pragma unroll
            for (int nf = 0; nf < 8; nf++) {
                const int bb = (wn + nf*8 + (lane>>2))*GP + k8*8 + (lane&3);
                bf[nf][0] = f2tf(Wb[bb]);
                bf[nf][1] = f2tf(Wb[bb + 4]);
            }
            #pragma unroll
            for (int nf = 0; nf < 8; nf++)
                #pragma unroll
                for (int mf = 0; mf < 4; mf++)
                    mma8(acc[mf][nf], af[mf], bf[nf][0], bf[nf][1]);
        }
        __syncthreads();
    }

    // Epilogue
    #pragma unroll
    for (int mf = 0; mf < 4; mf++) {
        const int m0 = bm + wm + mf*16 + (lane>>2);
        #pragma unroll
        for (int nf = 0; nf < 8; nf++) {
            const int n0 = bn + wn + nf*8 + 2*(lane&3);
            const float2 bv = *(const float2*)(bias + n0);
            *(float2*)(C + (size_t)m0 * DMODEL + n0) =
                make_float2(acc[mf][nf][0] + bv.x, acc[mf][nf][1] + bv.y);
            *(float2*)(C + (size_t)(m0+8) * DMODEL + n0) =
                make_float2(acc[mf][nf][2] + bv.x, acc[mf][nf][3] + bv.y);
        }
    }
}

__global__ __launch_bounds__(128, 2) void gemm_tf32(
    const float* __restrict__ A, const float* __restrict__ W,
    const float* __restrict__ bias, float* __restrict__ C)
{
    extern __shared__ __align__(16) float smg[];
    gemm_body(A, W, bias, C, smg);
}

__global__ __launch_bounds__(128, 2) void gemm_qkv(
    const float* __restrict__ q, const float* __restrict__ k,
    const float* __restrict__ v,
    const float* __restrict__ Wq, const float* __restrict__ bq,
    const float* __restrict__ Wk, const float* __restrict__ bk,
    const float* __restrict__ Wv, const float* __restrict__ bv,
    float* __restrict__ oq, float* __restrict__ ok, float* __restrict__ ov)
{
    extern __shared__ __align__(16) float smg[];
    const float* A; const float* W; const float* bias; float* C;
    if (blockIdx.z == 0)      { A = q; W = Wq; bias = bq; C = oq; }
    else if (blockIdx.z == 1) { A = k; W = Wk; bias = bk; C = ok; }
    else                      { A = v; W = Wv; bias = bv; C = ov; }
    gemm_body(A, W, bias, C, smg);
}

// ---------------------------------------------------------------------------
// Flash attention, tf32 mma. CTA = (b, h, 128-query tile); 64-key tiles.
// 8 warps x 16 query rows. Q/K/V staged raw f32 via cp.async; cvt at
// fragment load. V row-major (pitch 72: conflict-free B-frags). Softmax
// scale (1/32) applied inside the exponent.
// ---------------------------------------------------------------------------
#define QP 68
#define KP 68
#define VP 72

__global__ __launch_bounds__(256, 2) void flash_mma(
    const float* __restrict__ Q, const float* __restrict__ K,
    const float* __restrict__ V, float* __restrict__ O)
{
    extern __shared__ __align__(16) float smf[];
    float*    Qs  = smf;                 // [128][QP] raw f32
    float*    Ks  = Qs + 128*QP;         // [64][KP]  raw f32
    float*    Vs  = Ks + 64*KP;          // [64][VP]  raw f32, row-major (j,d)
    unsigned* Psu = (unsigned*)(Vs + 64*VP);  // [128][QP] tf32

    const int qt = gridDim.x - 1 - blockIdx.x;   // big tiles first
    const int h  = blockIdx.y;
    const int b  = blockIdx.z;
    const int tid  = threadIdx.x;
    const int lane = tid & 31;
    const int wid  = tid >> 5;
    const int qBase = qt * 128;

    const float* Qg  = Q + ((size_t)b * SEQ + qBase) * DMODEL + h * DHEAD;
    const float* Kg0 = K + ((size_t)b * SEQ) * DMODEL + h * DHEAD;
    const float* Vg0 = V + ((size_t)b * SEQ) * DMODEL + h * DHEAD;

    // Stage Q raw (cp.async): 128 rows x 64 d = 2048 float4, 8 per thread
    #pragma unroll
    for (int i = 0; i < 8; i++) {
        const int idx = i*256 + tid;
        const int row = idx >> 4;
        const int dc  = (idx & 15) * 4;
        cp16(&Qs[row*QP + dc], Qg + (size_t)row*DMODEL + dc);
    }
    CP_COMMIT;

    const int r0  = (wid << 4) + (lane >> 2);
    const int qi0 = qBase + r0;
    const int qi1 = qi0 + 8;

    float m0 = -1e30f, m1 = -1e30f, l0 = 0.0f, l1 = 0.0f;
    float o[8][4];
    #pragma unroll
    for (int nf = 0; nf < 8; nf++)
        #pragma unroll
        for (int e = 0; e < 4; e++) o[nf][e] = 0.0f;

    const float scale = 0.03125f;        // 1/sqrt(DMODEL)

    const int ktMax = 2*qt + 1;
    for (int kt = 0; kt <= ktMax; kt++) {
        const int kBase = kt * 64;
        __syncthreads();                 // prev iter done with Ks/Vs

        // Stage K, V raw: 64 rows x 64 d each -> 4 float4/thread/matrix
        #pragma unroll
        for (int i = 0; i < 4; i++) {
            const int idx = i*256 + tid;
            const int row = idx >> 4;
            const int dc  = (idx & 15) * 4;
            cp16(&Ks[row*KP + dc], Kg0 + (size_t)(kBase + row)*DMODEL + dc);
            cp16(&Vs[row*VP + dc], Vg0 + (size_t)(kBase + row)*DMODEL + dc);
        }
        CP_COMMIT;
        CP_WAIT0;
        __syncthreads();

        // S = Q @ K^T  (unscaled)
        float s[8][4];
        #pragma unroll
        for (int nf = 0; nf < 8; nf++)
            #pragma unroll
            for (int e = 0; e < 4; e++) s[nf][e] = 0.0f;

        #pragma unroll
        for (int k8 = 0; k8 < 8; k8++) {
            unsigned a[4];
            const int base = r0*QP + k8*8 + (lane&3);
            a[0] = f2tf(Qs[base]);
            a[1] = f2tf(Qs[base + 8*QP]);
            a[2] = f2tf(Qs[base + 4]);
            a[3] = f2tf(Qs[base + 8*QP + 4]);
            #pragma unroll
            for (int nf = 0; nf < 8; nf++) {
                const int bb = (nf*8 + (lane>>2))*KP + k8*8 + (lane&3);
                mma8(s[nf], a, f2tf(Ks[bb]), f2tf(Ks[bb + 4]));
            }
        }

        // Mask + online softmax (scale folded into exponent)
        const bool needMask = (kt >= 2*qt);
        float mt0 = -1e30f, mt1 = -1e30f;
        #pragma unroll
        for (int nf = 0; nf < 8; nf++) {
            #pragma unroll
            for (int e = 0; e < 2; e++) {
                if (needMask) {
                    const int kj = kBase + nf*8 + 2*(lane&3) + e;
                    if (kj > qi0) s[nf][e]   = -1e30f;
                    if (kj > qi1) s[nf][2+e] = -1e30f;
                }
                mt0 = fmaxf(mt0, s[nf][e]);
                mt1 = fmaxf(mt1, s[nf][2+e]);
            }
        }
        mt0 = fmaxf(mt0, __shfl_xor_sync(0xffffffffu, mt0, 1));
        mt0 = fmaxf(mt0, __shfl_xor_sync(0xffffffffu, mt0, 2));
        mt1 = fmaxf(mt1, __shfl_xor_sync(0xffffffffu, mt1, 1));
        mt1 = fmaxf(mt1, __shfl_xor_sync(0xffffffffu, mt1, 2));

        const float mn0 = fmaxf(m0, mt0);
        const float mn1 = fmaxf(m1, mt1);
        const float alpha0 = __expf((m0 - mn0) * scale);
        const float alpha1 = __expf((m1 - mn1) * scale);
        m0 = mn0; m1 = mn1;

        float ls0 = 0.0f, ls1 = 0.0f;
        #pragma unroll
        for (int nf = 0; nf < 8; nf++) {
            #pragma unroll
            for (int e = 0; e < 2; e++) {
                const float p0 = __expf((s[nf][e]   - mn0) * scale);
                const float p1 = __expf((s[nf][2+e] - mn1) * scale);
                s[nf][e]   = p0;
                s[nf][2+e] = p1;
                ls0 += p0; ls1 += p1;
            }
        }
        ls0 += __shfl_xor_sync(0xffffffffu, ls0, 1);
        ls0 += __shfl_xor_sync(0xffffffffu, ls0, 2);
        ls1 += __shfl_xor_sync(0xffffffffu, ls1, 1);
        ls1 += __shfl_xor_sync(0xffffffffu, ls1, 2);
        l0 = l0*alpha0 + ls0;
        l1 = l1*alpha1 + ls1;

        #pragma unroll
        for (int nf = 0; nf < 8; nf++) {
            o[nf][0] *= alpha0; o[nf][1] *= alpha0;
            o[nf][2] *= alpha1; o[nf][3] *= alpha1;
        }

        // P -> smem tf32 (warp-local round trip)
        __syncwarp();
        #pragma unroll
        for (int nf = 0; nf < 8; nf++) {
            const int col = nf*8 + 2*(lane&3);
            *(uint2*)&Psu[r0*QP + col] =
                make_uint2(f2tf(s[nf][0]), f2tf(s[nf][1]));
            *(uint2*)&Psu[(r0+8)*QP + col] =
                make_uint2(f2tf(s[nf][2]), f2tf(s[nf][3]));
        }
        __syncwarp();

        // O += P @ V   (V row-major: B[n=d][k=j] = Vs[j][d])
        #pragma unroll
        for (int k8 = 0; k8 < 8; k8++) {
            unsigned a[4];
            const int base = r0*QP + k8*8 + (lane&3);
            a[0] = Psu[base];
            a[1] = Psu[base + 8*QP];
            a[2] = Psu[base + 4];
            a[3] = Psu[base + 8*QP + 4];
            const int jrow = k8*8 + (lane&3);
            #pragma unroll
            for (int nf = 0; nf < 8; nf++) {
                const int col = nf*8 + (lane>>2);
                mma8(o[nf], a, f2tf(Vs[jrow*VP + col]),
                               f2tf(Vs[(jrow+4)*VP + col]));
            }
        }
    }

    // Normalize + write
    const float inv0 = 1.0f / l0;
    const float inv1 = 1.0f / l1;
    float* Ob = O + (size_t)b * SEQ * DMODEL + (size_t)h * DHEAD;
    #pragma unroll
    for (int nf = 0; nf < 8; nf++) {
        const int n = nf*8 + 2*(lane&3);
        *(float2*)(Ob + (size_t)qi0 * DMODEL + n) =
            make_float2(o[nf][0]*inv0, o[nf][1]*inv0);
        *(float2*)(Ob + (size_t)qi1 * DMODEL + n) =
            make_float2(o[nf][2]*inv1, o[nf][3]*inv1);
    }
}

// ---------------------------------------------------------------------------
extern "C" void kernel_launch(void* const* d_in, const int* in_sizes, int n_in,
                              void* d_out, int out_size)
{
    const float* q  = (const float*)d_in[0];
    const float* k  = (const float*)d_in[1];
    const float* v  = (const float*)d_in[2];
    const float* Wq = (const float*)d_in[3];
    const float* bq = (const float*)d_in[4];
    const float* Wk = (const float*)d_in[5];
    const float* bk = (const float*)d_in[6];
    const float* Wv = (const float*)d_in[7];
    const float* bv = (const float*)d_in[8];
    const float* Wo = (const float*)d_in[9];
    const float* bo = (const float*)d_in[10];
    float* out = (float*)d_out;

    float *qw, *kw, *vw, *att;
    cudaGetSymbolAddress((void**)&qw,  g_qw);
    cudaGetSymbolAddress((void**)&kw,  g_kw);
    cudaGetSymbolAddress((void**)&vw,  g_vw);
    cudaGetSymbolAddress((void**)&att, g_att);

    const int smemGemm  = 4 * GSM * (int)sizeof(float);               // 73728
    const int smemFlash = (128*QP + 64*KP + 64*VP + 128*QP) * 4;      // 105472
    cudaFuncSetAttribute(gemm_qkv,
                         cudaFuncAttributeMaxDynamicSharedMemorySize, smemGemm);
    cudaFuncSetAttribute(gemm_tf32,
                         cudaFuncAttributeMaxDynamicSharedMemorySize, smemGemm);
    cudaFuncSetAttribute(flash_mma,
                         cudaFuncAttributeMaxDynamicSharedMemorySize, smemFlash);

    dim3 gQKV(DMODEL/128, MROWS/128, 3);   // (8, 32, 3)
    gemm_qkv<<<gQKV, 128, smemGemm>>>(q, k, v, Wq, bq, Wk, bk, Wv, bv, qw, kw, vw);

    flash_mma<<<dim3(SEQ/128, NHEAD, BATCH), 256, smemFlash>>>(qw, kw, vw, att);

    dim3 gGemm(DMODEL/128, MROWS/128);     // (8, 32)
    gemm_tf32<<<gGemm, 128, smemGemm>>>(att, Wo, bo, out);
}

// round 5
// speedup vs baseline: 3.5028x; 1.0595x over previous
#include <cuda_runtime.h>
#include <math.h>

#define BATCH 2
#define SEQ 2048
#define DMODEL 1024
#define NHEAD 16
#define DHEAD 64
#define MROWS (BATCH*SEQ)   /* 4096 */

// Scratch (allocation-free)
__device__ float g_qr[MROWS*DMODEL];     // tf32-rounded inputs
__device__ float g_kr[MROWS*DMODEL];
__device__ float g_vr[MROWS*DMODEL];
__device__ float g_Wqr[DMODEL*DMODEL];   // tf32-rounded weights
__device__ float g_Wkr[DMODEL*DMODEL];
__device__ float g_Wvr[DMODEL*DMODEL];
__device__ float g_Wor[DMODEL*DMODEL];
__device__ float g_qw[MROWS*DMODEL];     // projections (tf32-rounded)
__device__ float g_kw[MROWS*DMODEL];
__device__ float g_vw[MROWS*DMODEL];
__device__ float g_att[MROWS*DMODEL];    // attention out (tf32-rounded)

// ---------------------------------------------------------------------------
// Helpers
// ---------------------------------------------------------------------------
__device__ __forceinline__ unsigned f2tf(float x) {
    unsigned r;
    asm("cvt.rna.tf32.f32 %0, %1;" : "=r"(r) : "f"(x));
    return r;
}
__device__ __forceinline__ float rnd_tf32(float x) {
    return __uint_as_float(f2tf(x));
}
__device__ __forceinline__ float ex2(float x) {
    float r;
    asm("ex2.approx.f32 %0, %1;" : "=f"(r) : "f"(x));
    return r;
}

__device__ __forceinline__ void mma8(float* d, const unsigned* a,
                                     unsigned b0, unsigned b1) {
    asm volatile(
        "mma.sync.aligned.m16n8k8.row.col.f32.tf32.tf32.f32 "
        "{%0,%1,%2,%3}, {%4,%5,%6,%7}, {%8,%9}, {%0,%1,%2,%3};"
        : "+f"(d[0]), "+f"(d[1]), "+f"(d[2]), "+f"(d[3])
        : "r"(a[0]), "r"(a[1]), "r"(a[2]), "r"(a[3]), "r"(b0), "r"(b1));
}

__device__ __forceinline__ void cp16(const void* smem_dst, const void* gsrc) {
    unsigned d = (unsigned)__cvta_generic_to_shared(smem_dst);
    asm volatile("cp.async.cg.shared.global [%0], [%1], 16;" :: "r"(d), "l"(gsrc));
}
#define CP_COMMIT asm volatile("cp.async.commit_group;")
#define CP_WAIT0  asm volatile("cp.async.wait_group 0;")
#define CP_WAIT1  asm volatile("cp.async.wait_group 1;")

// ---------------------------------------------------------------------------
// Pre-round: copy tensors with tf32 rounding. blockIdx.y selects tensor.
// ---------------------------------------------------------------------------
__global__ __launch_bounds__(256) void pre_round(
    const float* __restrict__ q, const float* __restrict__ k,
    const float* __restrict__ v,
    const float* __restrict__ Wq, const float* __restrict__ Wk,
    const float* __restrict__ Wv, const float* __restrict__ Wo)
{
    const float* src; float* dst; int n;
    switch (blockIdx.y) {
        case 0: src = q;  dst = g_qr;  n = MROWS*DMODEL;  break;
        case 1: src = k;  dst = g_kr;  n = MROWS*DMODEL;  break;
        case 2: src = v;  dst = g_vr;  n = MROWS*DMODEL;  break;
        case 3: src = Wq; dst = g_Wqr; n = DMODEL*DMODEL; break;
        case 4: src = Wk; dst = g_Wkr; n = DMODEL*DMODEL; break;
        case 5: src = Wv; dst = g_Wvr; n = DMODEL*DMODEL; break;
        default: src = Wo; dst = g_Wor; n = DMODEL*DMODEL; break;
    }
    const int idx = (blockIdx.x * 256 + threadIdx.x) * 4;
    if (idx < n) {
        float4 x = *(const float4*)(src + idx);
        *(float4*)(dst + idx) = make_float4(
            rnd_tf32(x.x), rnd_tf32(x.y), rnd_tf32(x.z), rnd_tf32(x.w));
    }
}

// ---------------------------------------------------------------------------
// GEMM: C[m,n] = sum_k A[m,k]*W[n,k] + bias[n].  A, W pre-rounded to tf32.
// CTA 128x128, BK=32 double-buffered cp.async, 4 warps (2x2) of 64x64.
// Fragment loads are raw-bit LDS -> HMMA (no cvt).
// ---------------------------------------------------------------------------
#define GP 36
#define GSM (128*GP)

template<int ROUND_OUT>
__device__ __forceinline__ void gemm_body(
    const float* __restrict__ A, const float* __restrict__ W,
    const float* __restrict__ bias, float* __restrict__ C, float* sm)
{
    float* As = sm;            // [2][128*GP]
    float* Ws = sm + 2*GSM;    // [2][128*GP]

    const int tid  = threadIdx.x;
    const int lane = tid & 31;
    const int wid  = tid >> 5;           // 0..3
    const int bm = blockIdx.y * 128;
    const int bn = blockIdx.x * 128;
    const int wm = (wid & 1) * 64;
    const int wn = (wid >> 1) * 64;

    const float* Ag = A + (size_t)bm * DMODEL;
    const float* Wg = W + (size_t)bn * DMODEL;

    float acc[4][8][4];
    #pragma unroll
    for (int mf = 0; mf < 4; mf++)
        #pragma unroll
        for (int nf = 0; nf < 8; nf++)
            #pragma unroll
            for (int e = 0; e < 4; e++) acc[mf][nf][e] = 0.0f;

    auto stage = [&](int buf, int k0) {
        #pragma unroll
        for (int i = 0; i < 8; i++) {
            const int idx = i*128 + tid;
            const int row = idx >> 3;
            const int kc  = (idx & 7) * 4;
            cp16(&As[buf*GSM + row*GP + kc], Ag + (size_t)row*DMODEL + k0 + kc);
            cp16(&Ws[buf*GSM + row*GP + kc], Wg + (size_t)row*DMODEL + k0 + kc);
        }
        CP_COMMIT;
    };

    stage(0, 0);

    const int ntiles = DMODEL / 32;      // 32
    for (int kt = 0; kt < ntiles; kt++) {
        const int cur = kt & 1;
        if (kt + 1 < ntiles) {
            stage(cur ^ 1, (kt + 1) * 32);
            CP_WAIT1;
        } else {
            CP_WAIT0;
        }
        __syncthreads();

        const unsigned* Ab = (const unsigned*)(As + cur*GSM);
        const unsigned* Wb = (const unsigned*)(Ws + cur*GSM);
        #pragma unroll
        for (int k8 = 0; k8 < 4; k8++) {
            unsigned af[4][4];
            #pragma unroll
            for (int mf = 0; mf < 4; mf++) {
                const int base = (wm + mf*16 + (lane>>2))*GP + k8*8 + (lane&3);
                af[mf][0] = Ab[base];
                af[mf][1] = Ab[base + 8*GP];
                af[mf][2] = Ab[base + 4];
                af[mf][3] = Ab[base + 8*GP + 4];
            }
            unsigned bf[8][2];
            #pragma unroll
            for (int nf = 0; nf < 8; nf++) {
                const int bb = (wn + nf*8 + (lane>>2))*GP + k8*8 + (lane&3);
                bf[nf][0] = Wb[bb];
                bf[nf][1] = Wb[bb + 4];
            }
            #pragma unroll
            for (int nf = 0; nf < 8; nf++)
                #pragma unroll
                for (int mf = 0; mf < 4; mf++)
                    mma8(acc[mf][nf], af[mf], bf[nf][0], bf[nf][1]);
        }
        __syncthreads();
    }

    // Epilogue
    #pragma unroll
    for (int mf = 0; mf < 4; mf++) {
        const int m0 = bm + wm + mf*16 + (lane>>2);
        #pragma unroll
        for (int nf = 0; nf < 8; nf++) {
            const int n0 = bn + wn + nf*8 + 2*(lane&3);
            const float2 bv = *(const float2*)(bias + n0);
            float r00 = acc[mf][nf][0] + bv.x, r01 = acc[mf][nf][1] + bv.y;
            float r10 = acc[mf][nf][2] + bv.x, r11 = acc[mf][nf][3] + bv.y;
            if (ROUND_OUT) {
                r00 = rnd_tf32(r00); r01 = rnd_tf32(r01);
                r10 = rnd_tf32(r10); r11 = rnd_tf32(r11);
            }
            *(float2*)(C + (size_t)m0 * DMODEL + n0)     = make_float2(r00, r01);
            *(float2*)(C + (size_t)(m0+8) * DMODEL + n0) = make_float2(r10, r11);
        }
    }
}

__global__ __launch_bounds__(128, 2) void gemm_out(
    const float* __restrict__ A, const float* __restrict__ W,
    const float* __restrict__ bias, float* __restrict__ C)
{
    extern __shared__ __align__(16) float smg[];
    gemm_body<0>(A, W, bias, C, smg);
}

__global__ __launch_bounds__(128, 2) void gemm_qkv(
    const float* __restrict__ bq, const float* __restrict__ bk,
    const float* __restrict__ bv)
{
    extern __shared__ __align__(16) float smg[];
    const float* A; const float* W; const float* bias; float* C;
    if (blockIdx.z == 0)      { A = g_qr; W = g_Wqr; bias = bq; C = g_qw; }
    else if (blockIdx.z == 1) { A = g_kr; W = g_Wkr; bias = bk; C = g_kw; }
    else                      { A = g_vr; W = g_Wvr; bias = bv; C = g_vw; }
    gemm_body<1>(A, W, bias, C, smg);
}

// ---------------------------------------------------------------------------
// Flash attention, tf32 mma. CTA = (b, h, 128-query tile); 64-key tiles.
// Q/K/V pre-rounded: fragments are raw-bit LDS. Only P is cvt'd (post-exp).
// scale applied inside the exponent via ex2.approx.
// ---------------------------------------------------------------------------
#define QP 68
#define KP 68
#define VP 72

__global__ __launch_bounds__(256, 2) void flash_mma(
    const float* __restrict__ Q, const float* __restrict__ K,
    const float* __restrict__ V, float* __restrict__ O)
{
    extern __shared__ __align__(16) float smf[];
    float*    Qs  = smf;                 // [128][QP] tf32-valued f32
    float*    Ks  = Qs + 128*QP;         // [64][KP]
    float*    Vs  = Ks + 64*KP;          // [64][VP] row-major (j,d)
    unsigned* Psu = (unsigned*)(Vs + 64*VP);  // [128][QP] tf32

    const int qt = gridDim.x - 1 - blockIdx.x;   // big tiles first
    const int h  = blockIdx.y;
    const int b  = blockIdx.z;
    const int tid  = threadIdx.x;
    const int lane = tid & 31;
    const int wid  = tid >> 5;
    const int qBase = qt * 128;

    const float* Qg  = Q + ((size_t)b * SEQ + qBase) * DMODEL + h * DHEAD;
    const float* Kg0 = K + ((size_t)b * SEQ) * DMODEL + h * DHEAD;
    const float* Vg0 = V + ((size_t)b * SEQ) * DMODEL + h * DHEAD;

    // Stage Q: 128 rows x 64 d = 2048 float4, 8 per thread
    #pragma unroll
    for (int i = 0; i < 8; i++) {
        const int idx = i*256 + tid;
        const int row = idx >> 4;
        const int dc  = (idx & 15) * 4;
        cp16(&Qs[row*QP + dc], Qg + (size_t)row*DMODEL + dc);
    }
    CP_COMMIT;

    const int r0  = (wid << 4) + (lane >> 2);
    const int qi0 = qBase + r0;
    const int qi1 = qi0 + 8;

    float m0 = -1e30f, m1 = -1e30f, l0 = 0.0f, l1 = 0.0f;
    float o[8][4];
    #pragma unroll
    for (int nf = 0; nf < 8; nf++)
        #pragma unroll
        for (int e = 0; e < 4; e++) o[nf][e] = 0.0f;

    const float c2 = 0.03125f * 1.4426950408889634f;  // scale * log2(e)

    const int ktMax = 2*qt + 1;
    for (int kt = 0; kt <= ktMax; kt++) {
        const int kBase = kt * 64;
        __syncthreads();                 // prev iter done with Ks/Vs

        #pragma unroll
        for (int i = 0; i < 4; i++) {
            const int idx = i*256 + tid;
            const int row = idx >> 4;
            const int dc  = (idx & 15) * 4;
            cp16(&Ks[row*KP + dc], Kg0 + (size_t)(kBase + row)*DMODEL + dc);
            cp16(&Vs[row*VP + dc], Vg0 + (size_t)(kBase + row)*DMODEL + dc);
        }
        CP_COMMIT;
        CP_WAIT0;
        __syncthreads();

        // S = Q @ K^T (unscaled) — raw-bit fragments
        float s[8][4];
        #pragma unroll
        for (int nf = 0; nf < 8; nf++)
            #pragma unroll
            for (int e = 0; e < 4; e++) s[nf][e] = 0.0f;

        const unsigned* Qb = (const unsigned*)Qs;
        const unsigned* Kb = (const unsigned*)Ks;
        const unsigned* Vb = (const unsigned*)Vs;

        #pragma unroll
        for (int k8 = 0; k8 < 8; k8++) {
            unsigned a[4];
            const int base = r0*QP + k8*8 + (lane&3);
            a[0] = Qb[base];
            a[1] = Qb[base + 8*QP];
            a[2] = Qb[base + 4];
            a[3] = Qb[base + 8*QP + 4];
            #pragma unroll
            for (int nf = 0; nf < 8; nf++) {
                const int bb = (nf*8 + (lane>>2))*KP + k8*8 + (lane&3);
                mma8(s[nf], a, Kb[bb], Kb[bb + 4]);
            }
        }

        // Mask + online softmax
        const bool needMask = (kt >= 2*qt);
        float mt0 = -1e30f, mt1 = -1e30f;
        #pragma unroll
        for (int nf = 0; nf < 8; nf++) {
            #pragma unroll
            for (int e = 0; e < 2; e++) {
                if (needMask) {
                    const int kj = kBase + nf*8 + 2*(lane&3) + e;
                    if (kj > qi0) s[nf][e]   = -1e30f;
                    if (kj > qi1) s[nf][2+e] = -1e30f;
                }
                mt0 = fmaxf(mt0, s[nf][e]);
                mt1 = fmaxf(mt1, s[nf][2+e]);
            }
        }
        mt0 = fmaxf(mt0, __shfl_xor_sync(0xffffffffu, mt0, 1));
        mt0 = fmaxf(mt0, __shfl_xor_sync(0xffffffffu, mt0, 2));
        mt1 = fmaxf(mt1, __shfl_xor_sync(0xffffffffu, mt1, 1));
        mt1 = fmaxf(mt1, __shfl_xor_sync(0xffffffffu, mt1, 2));

        const float mn0 = fmaxf(m0, mt0);
        const float mn1 = fmaxf(m1, mt1);
        const float alpha0 = ex2((m0 - mn0) * c2);
        const float alpha1 = ex2((m1 - mn1) * c2);
        m0 = mn0; m1 = mn1;

        float ls0 = 0.0f, ls1 = 0.0f;
        #pragma unroll
        for (int nf = 0; nf < 8; nf++) {
            #pragma unroll
            for (int e = 0; e < 2; e++) {
                const float p0 = ex2((s[nf][e]   - mn0) * c2);
                const float p1 = ex2((s[nf][2+e] - mn1) * c2);
                s[nf][e]   = p0;
                s[nf][2+e] = p1;
                ls0 += p0; ls1 += p1;
            }
        }
        ls0 += __shfl_xor_sync(0xffffffffu, ls0, 1);
        ls0 += __shfl_xor_sync(0xffffffffu, ls0, 2);
        ls1 += __shfl_xor_sync(0xffffffffu, ls1, 1);
        ls1 += __shfl_xor_sync(0xffffffffu, ls1, 2);
        l0 = l0*alpha0 + ls0;
        l1 = l1*alpha1 + ls1;

        #pragma unroll
        for (int nf = 0; nf < 8; nf++) {
            o[nf][0] *= alpha0; o[nf][1] *= alpha0;
            o[nf][2] *= alpha1; o[nf][3] *= alpha1;
        }

        // P -> smem tf32 (warp-local round trip)
        __syncwarp();
        #pragma unroll
        for (int nf = 0; nf < 8; nf++) {
            const int col = nf*8 + 2*(lane&3);
            *(uint2*)&Psu[r0*QP + col] =
                make_uint2(f2tf(s[nf][0]), f2tf(s[nf][1]));
            *(uint2*)&Psu[(r0+8)*QP + col] =
                make_uint2(f2tf(s[nf][2]), f2tf(s[nf][3]));
        }
        __syncwarp();

        // O += P @ V   (V row-major: B[n=d][k=j] = Vs[j][d])
        #pragma unroll
        for (int k8 = 0; k8 < 8; k8++) {
            unsigned a[4];
            const int base = r0*QP + k8*8 + (lane&3);
            a[0] = Psu[base];
            a[1] = Psu[base + 8*QP];
            a[2] = Psu[base + 4];
            a[3] = Psu[base + 8*QP + 4];
            const int jrow = k8*8 + (lane&3);
            #pragma unroll
            for (int nf = 0; nf < 8; nf++) {
                const int col = nf*8 + (lane>>2);
                mma8(o[nf], a, Vb[jrow*VP + col], Vb[(jrow+4)*VP + col]);
            }
        }
    }

    // Normalize + write (tf32-rounded: consumer GEMM skips cvt)
    const float inv0 = 1.0f / l0;
    const float inv1 = 1.0f / l1;
    float* Ob = O + (size_t)b * SEQ * DMODEL + (size_t)h * DHEAD;
    #pragma unroll
    for (int nf = 0; nf < 8; nf++) {
        const int n = nf*8 + 2*(lane&3);
        *(float2*)(Ob + (size_t)qi0 * DMODEL + n) =
            make_float2(rnd_tf32(o[nf][0]*inv0), rnd_tf32(o[nf][1]*inv0));
        *(float2*)(Ob + (size_t)qi1 * DMODEL + n) =
            make_float2(rnd_tf32(o[nf][2]*inv1), rnd_tf32(o[nf][3]*inv1));
    }
}

// ---------------------------------------------------------------------------
extern "C" void kernel_launch(void* const* d_in, const int* in_sizes, int n_in,
                              void* d_out, int out_size)
{
    const float* q  = (const float*)d_in[0];
    const float* k  = (const float*)d_in[1];
    const float* v  = (const float*)d_in[2];
    const float* Wq = (const float*)d_in[3];
    const float* bq = (const float*)d_in[4];
    const float* Wk = (const float*)d_in[5];
    const float* bk = (const float*)d_in[6];
    const float* Wv = (const float*)d_in[7];
    const float* bv = (const float*)d_in[8];
    const float* Wo = (const float*)d_in[9];
    const float* bo = (const float*)d_in[10];
    float* out = (float*)d_out;

    float *qw, *kw, *vw, *att, *Wor;
    cudaGetSymbolAddress((void**)&qw,  g_qw);
    cudaGetSymbolAddress((void**)&kw,  g_kw);
    cudaGetSymbolAddress((void**)&vw,  g_vw);
    cudaGetSymbolAddress((void**)&att, g_att);
    cudaGetSymbolAddress((void**)&Wor, g_Wor);

    const int smemGemm  = 4 * GSM * (int)sizeof(float);               // 73728
    const int smemFlash = (128*QP + 64*KP + 64*VP + 128*QP) * 4;      // 105472
    cudaFuncSetAttribute(gemm_qkv,
                         cudaFuncAttributeMaxDynamicSharedMemorySize, smemGemm);
    cudaFuncSetAttribute(gemm_out,
                         cudaFuncAttributeMaxDynamicSharedMemorySize, smemGemm);
    cudaFuncSetAttribute(flash_mma,
                         cudaFuncAttributeMaxDynamicSharedMemorySize, smemFlash);

    // 1) tf32 pre-round of inputs + weights
    pre_round<<<dim3(MROWS*DMODEL/(256*4), 7), 256>>>(q, k, v, Wq, Wk, Wv, Wo);

    // 2) fused QKV projections
    dim3 gQKV(DMODEL/128, MROWS/128, 3);
    gemm_qkv<<<gQKV, 128, smemGemm>>>(bq, bk, bv);

    // 3) causal flash attention
    flash_mma<<<dim3(SEQ/128, NHEAD, BATCH), 256, smemFlash>>>(qw, kw, vw, att);

    // 4) output projection
    dim3 gGemm(DMODEL/128, MROWS/128);
    gemm_out<<<gGemm, 128, smemGemm>>>(att, Wor, bo, out);
}